// round 8
// baseline (speedup 1.0000x reference)
#include <cuda_runtime.h>
#include <cuda_bf16.h>
#include <cstdint>

// Problem constants
constexpr int BATCH = 2048;
constexpr int NF    = 512;
constexpr int FD    = 64;
constexpr int NOUT  = 8;
constexpr int BM    = 128;   // M-tile per block

// fp32 activation ping-pong (2 x 256 MB)
__device__ __align__(256) float g_x0[BATCH * NF * FD];
__device__ __align__(256) float g_x1[BATCH * NF * FD];
// Pre-split transposed weights: Wt[n][k] = W[k][n], bf16 hi/lo planes.
// Per fold: 64 rows(n) x 64 k packed as 512 uint4 (8 bf16 each).
__device__ __align__(256) uint4 g_wh[4 * 512 * 512];
__device__ __align__(256) uint4 g_wl[4 * 512 * 512];

// SW128 swizzle (Swizzle<3,4,3>) on byte offsets with 128B rows
#define SW(o) ((o) ^ ((((unsigned)(o)) >> 3) & 0x70))

__device__ __forceinline__ uint32_t smem_u32(const void* p) {
    uint32_t a;
    asm("{ .reg .u64 t; cvta.to.shared.u64 t, %1; cvt.u32.u64 %0, t; }" : "=r"(a) : "l"(p));
    return a;
}
__device__ __forceinline__ uint32_t pack_hi_lo(float a, float b, uint32_t& lo) {
    __nv_bfloat162 h2 = __floats2bfloat162_rn(a, b);
    float ra = a - __bfloat162float(h2.x);
    float rb = b - __bfloat162float(h2.y);
    __nv_bfloat162 l2 = __floats2bfloat162_rn(ra, rb);
    lo = *reinterpret_cast<uint32_t*>(&l2);
    return *reinterpret_cast<uint32_t*>(&h2);
}
__device__ __forceinline__ void ldsm_x4(uint32_t* r, uint32_t addr) {
    asm volatile("ldmatrix.sync.aligned.m8n8.x4.shared.b16 {%0,%1,%2,%3}, [%4];"
                 : "=r"(r[0]), "=r"(r[1]), "=r"(r[2]), "=r"(r[3]) : "r"(addr));
}
__device__ __forceinline__ void mma_bf16(float* c, const uint32_t* a,
                                         uint32_t b0, uint32_t b1) {
    asm volatile(
        "mma.sync.aligned.m16n8k16.row.col.f32.bf16.bf16.f32 "
        "{%0,%1,%2,%3}, {%4,%5,%6,%7}, {%8,%9}, {%0,%1,%2,%3};"
        : "+f"(c[0]), "+f"(c[1]), "+f"(c[2]), "+f"(c[3])
        : "r"(a[0]), "r"(a[1]), "r"(a[2]), "r"(a[3]), "r"(b0), "r"(b1));
}

// ---------------- weight prep: transpose + bf16 hi/lo split ----------------
__global__ void wprep_kernel(const float* __restrict__ W) {
    __shared__ float s[64][65];
    const int lf = blockIdx.x;                 // layer*512 + fold
    const float4* Wf4 = reinterpret_cast<const float4*>(W + (size_t)lf * 4096);
    for (int i = threadIdx.x; i < 1024; i += 256) {
        const int k = i >> 4, nq = i & 15;
        float4 v = Wf4[i];
        s[k][nq * 4 + 0] = v.x; s[k][nq * 4 + 1] = v.y;
        s[k][nq * 4 + 2] = v.z; s[k][nq * 4 + 3] = v.w;
    }
    __syncthreads();
    for (int i = threadIdx.x; i < 512; i += 256) {
        const int n = i >> 3, kq = i & 7;      // out row n, 8-k chunk kq
        uint32_t hw[4], lw[4];
        #pragma unroll
        for (int j = 0; j < 4; j++) {
            const float a = s[kq * 8 + j * 2 + 0][n];
            const float b = s[kq * 8 + j * 2 + 1][n];
            hw[j] = pack_hi_lo(a, b, lw[j]);
        }
        g_wh[(size_t)lf * 512 + i] = make_uint4(hw[0], hw[1], hw[2], hw[3]);
        g_wl[(size_t)lf * 512 + i] = make_uint4(lw[0], lw[1], lw[2], lw[3]);
    }
}

// ---------------- HMMA layer kernel (512 threads, 16 warps) ----------------
// Dynamic smem map (bytes): HH 0 (16K), HL 16384 (16K), WH 32768 (8K), WL 40960 (8K).
constexpr int SM_HH = 0, SM_HL = 16384, SM_WH = 32768, SM_WL = 40960;
constexpr int SMEM_BYTES = 49152;

__global__ __launch_bounds__(512, 2)
void layer_mma_kernel(const float* __restrict__ xin,
                      const uint4* __restrict__ wh,   // this layer: [512 folds][512] uint4
                      const uint4* __restrict__ wl,
                      const int*   __restrict__ fidx,
                      float*       __restrict__ xout)
{
    extern __shared__ char smem[];
    const uint32_t sb = smem_u32(smem);
    const int tid = threadIdx.x, wid = tid >> 5, lid = tid & 31;
    const int f = blockIdx.x, m0 = blockIdx.y * BM;

    // --- W tiles (pre-transposed bf16 hi/lo): copy with SW128 swizzle ---
    const uint4* whf = wh + (size_t)f * 512;
    const uint4* wlf = wl + (size_t)f * 512;
    {
        const int i = tid;                     // 0..511
        const int n = i >> 3, q = i & 7;
        const uint32_t off = SW(n * 128 + q * 16);
        *reinterpret_cast<uint4*>(smem + SM_WH + off) = whf[i];
        *reinterpret_cast<uint4*>(smem + SM_WL + off) = wlf[i];
    }

    // --- H tiles: gather + product (fp32), split to bf16 hi/lo, swizzled store ---
    const float* x0 = xin + (size_t)fidx[2 * f + 0] * FD;
    const float* x1 = xin + (size_t)fidx[2 * f + 1] * FD;
    #pragma unroll
    for (int it = 0; it < 2; it++) {
        const int i = it * 512 + tid;          // 0..1023
        const int m = i >> 3, q = i & 7;       // row m (0..127), 8-k chunk q
        const size_t boff = (size_t)(m0 + m) * (NF * FD) + q * 8;
        const float4 a0 = *reinterpret_cast<const float4*>(x0 + boff);
        const float4 a1 = *reinterpret_cast<const float4*>(x0 + boff + 4);
        const float4 b0 = *reinterpret_cast<const float4*>(x1 + boff);
        const float4 b1 = *reinterpret_cast<const float4*>(x1 + boff + 4);
        const float p[8] = { a0.x * b0.x, a0.y * b0.y, a0.z * b0.z, a0.w * b0.w,
                             a1.x * b1.x, a1.y * b1.y, a1.z * b1.z, a1.w * b1.w };
        uint32_t hw[4], lw[4];
        #pragma unroll
        for (int j = 0; j < 4; j++)
            hw[j] = pack_hi_lo(p[2 * j], p[2 * j + 1], lw[j]);
        const uint32_t off = SW(m * 128 + q * 16);
        *reinterpret_cast<uint4*>(smem + SM_HH + off) = make_uint4(hw[0], hw[1], hw[2], hw[3]);
        *reinterpret_cast<uint4*>(smem + SM_HL + off) = make_uint4(lw[0], lw[1], lw[2], lw[3]);
    }
    __syncthreads();

    // --- warp-tiled MMA: 16 warps, warp tile 16(M) x 32(N) ---
    const int wm = wid >> 1;                   // 0..7 -> m offset wm*16
    const int wn = wid & 1;                    // 0..1 -> n offset wn*32
    const int l7 = lid & 7, l8 = (lid >> 3) & 1, l16 = lid >> 4;

    float acc[4][4];                           // [nt][frag] — 16 fp32
    #pragma unroll
    for (int nt = 0; nt < 4; nt++)
        #pragma unroll
        for (int j = 0; j < 4; j++)
            acc[nt][j] = 0.0f;

    #pragma unroll
    for (int ks = 0; ks < 4; ks++) {
        const int kc = ks * 16 + l16 * 8;      // k column for this lane's ldmatrix
        uint32_t AH[4], AL[4], BH[2][4], BL[2][4];
        {
            const int row = wm * 16 + l7 + l8 * 8;
            const uint32_t off = SW(row * 128 + kc * 2);
            ldsm_x4(AH, sb + SM_HH + off);
            ldsm_x4(AL, sb + SM_HL + off);
        }
        #pragma unroll
        for (int h = 0; h < 2; h++) {
            const int n = wn * 32 + h * 16 + l7 + l8 * 8;
            const uint32_t off = SW(n * 128 + kc * 2);
            ldsm_x4(BH[h], sb + SM_WH + off);
            ldsm_x4(BL[h], sb + SM_WL + off);
        }
        #pragma unroll
        for (int nt = 0; nt < 4; nt++) {
            const int h = nt >> 1, s = nt & 1;
            mma_bf16(acc[nt], AH, BH[h][s], BH[h][s + 2]);
            mma_bf16(acc[nt], AH, BL[h][s], BL[h][s + 2]);
            mma_bf16(acc[nt], AL, BH[h][s], BH[h][s + 2]);
        }
    }

    // --- epilogue: fragment -> GMEM (float2 stores) ---
    const int quad = lid >> 2, qlane = lid & 3;
    const int r = m0 + wm * 16 + quad;
    #pragma unroll
    for (int nt = 0; nt < 4; nt++) {
        const int col = f * FD + wn * 32 + nt * 8 + qlane * 2;
        float* d0 = xout + (size_t)r * (NF * FD) + col;
        float* d1 = d0 + (size_t)8 * (NF * FD);
        *reinterpret_cast<float2*>(d0) = make_float2(acc[nt][0], acc[nt][1]);
        *reinterpret_cast<float2*>(d1) = make_float2(acc[nt][2], acc[nt][3]);
    }
}

// Final gather: out[b, o, :] = x[b, out_idx[o], :]
__global__ void gather_kernel(const float* __restrict__ x,
                              const int* __restrict__ oidx,
                              float* __restrict__ out)
{
    const int t = blockIdx.x * blockDim.x + threadIdx.x;
    const int total = BATCH * NOUT * (FD / 4);
    if (t >= total) return;
    const int q = t & 15;
    const int o = (t >> 4) & (NOUT - 1);
    const int b = t >> 7;
    const size_t src = (size_t)b * (NF * FD) + (size_t)oidx[o] * FD + q * 4;
    reinterpret_cast<float4*>(out)[t] = *reinterpret_cast<const float4*>(x + src);
}

extern "C" void kernel_launch(void* const* d_in, const int* in_sizes, int n_in,
                              void* d_out, int out_size)
{
    const float* in_graph = (const float*)d_in[0];
    const float* weights  = (const float*)d_in[1];
    const int*   fold_idx = (const int*)d_in[2];
    const int*   out_idx  = (const int*)d_in[3];
    float*       out      = (float*)d_out;

    float *p0 = nullptr, *p1 = nullptr;
    uint4 *wh = nullptr, *wl = nullptr;
    cudaGetSymbolAddress((void**)&p0, g_x0);
    cudaGetSymbolAddress((void**)&p1, g_x1);
    cudaGetSymbolAddress((void**)&wh, g_wh);
    cudaGetSymbolAddress((void**)&wl, g_wl);

    cudaFuncSetAttribute(layer_mma_kernel,
                         cudaFuncAttributeMaxDynamicSharedMemorySize, SMEM_BYTES);

    // Pre-split + transpose all layer weights into bf16 hi/lo
    wprep_kernel<<<4 * 512, 256>>>(weights);

    const size_t wlayer = (size_t)512 * 512;   // uint4 per layer
    const size_t i_stride = (size_t)NF * 2;

    dim3 grid(NF, BATCH / BM);
    dim3 block(512);

    layer_mma_kernel<<<grid, block, SMEM_BYTES>>>(in_graph, wh + 0 * wlayer, wl + 0 * wlayer,
                                                  fold_idx + 0 * i_stride, p0);
    layer_mma_kernel<<<grid, block, SMEM_BYTES>>>(p0, wh + 1 * wlayer, wl + 1 * wlayer,
                                                  fold_idx + 1 * i_stride, p1);
    layer_mma_kernel<<<grid, block, SMEM_BYTES>>>(p1, wh + 2 * wlayer, wl + 2 * wlayer,
                                                  fold_idx + 2 * i_stride, p0);
    layer_mma_kernel<<<grid, block, SMEM_BYTES>>>(p0, wh + 3 * wlayer, wl + 3 * wlayer,
                                                  fold_idx + 3 * i_stride, p1);

    const int total = BATCH * NOUT * (FD / 4);
    gather_kernel<<<(total + 255) / 256, 256>>>(p1, out_idx, out);
}